// round 4
// baseline (speedup 1.0000x reference)
#include <cuda_runtime.h>
#include <math_constants.h>

#define M_ROWS 131072
#define N_VERTS 4000
#define DIMS 16
#define NPAIRS (N_VERTS / 2)          // 2000
#define SLOTS 18                      // f32x2 slots/pair: (-h/2) + 16 dims + pad = 144B
#define TILE_PAIRS 1000
#define NTILES (NPAIRS / TILE_PAIRS)  // 2
#define BLOCK 512
#define QROWS 2
#define SMEM_BYTES (TILE_PAIRS * SLOTS * 8)

// Packed verts scratch: [pair][slot] of f32x2. 2000*18*8 = 288 KB.
__device__ float2 g_packed[NPAIRS * SLOTS];

__global__ void prep_kernel(const float* __restrict__ verts_emb) {
    int p = blockIdx.x * blockDim.x + threadIdx.x;
    if (p >= NPAIRS) return;
    const float* y0 = verts_emb + (size_t)(2 * p) * DIMS;
    const float* y1 = verts_emb + (size_t)(2 * p + 1) * DIMS;
    float h0 = 0.f, h1 = 0.f;
    float2* dst = g_packed + (size_t)p * SLOTS;
#pragma unroll
    for (int d = 0; d < DIMS; ++d) {
        float a = y0[d], b = y1[d];
        h0 += a * a;
        h1 += b * b;
        dst[1 + d] = make_float2(a, b);
    }
    dst[0]  = make_float2(-0.5f * h0, -0.5f * h1);
    dst[17] = make_float2(0.f, 0.f);  // pad
}

// ---- packed f32x2 helpers (FFMA2 only reachable via PTX fma.rn.f32x2) ----
__device__ __forceinline__ void fma2(unsigned long long& acc,
                                     unsigned long long a,
                                     unsigned long long b) {
    asm("fma.rn.f32x2 %0, %1, %2, %0;" : "+l"(acc) : "l"(a), "l"(b));
}
__device__ __forceinline__ unsigned long long bcast2(float v) {
    unsigned long long r;
    unsigned int u = __float_as_uint(v);
    asm("mov.b64 %0, {%1, %1};" : "=l"(r) : "r"(u));
    return r;
}
__device__ __forceinline__ void unpack2(unsigned long long v, float& lo, float& hi) {
    unsigned int l, h;
    asm("mov.b64 {%0, %1}, %2;" : "=r"(l), "=r"(h) : "l"(v));
    lo = __int_as_float(l);
    hi = __int_as_float(h);
}

struct Buf {
    ulonglong2 v[9];
};

__device__ __forceinline__ void load_pair(Buf& b, const ulonglong2* pp) {
#pragma unroll
    for (int j = 0; j < 9; ++j) b.v[j] = pp[j];
}

// Compute both query scores (packed over the vert pair) from one buffer.
__device__ __forceinline__ void score_pair(const Buf& b,
                                           const unsigned long long* X0,
                                           const unsigned long long* X1,
                                           unsigned long long& a0,
                                           unsigned long long& a1) {
    a0 = b.v[0].x;  // (-h/2, -h/2) per-lane init
    a1 = b.v[0].x;
    fma2(a0, X0[0], b.v[0].y);
    fma2(a1, X1[0], b.v[0].y);
#pragma unroll
    for (int j = 1; j < 8; ++j) {
        fma2(a0, X0[2 * j - 1], b.v[j].x);
        fma2(a0, X0[2 * j],     b.v[j].y);
        fma2(a1, X1[2 * j - 1], b.v[j].x);
        fma2(a1, X1[2 * j],     b.v[j].y);
    }
    fma2(a0, X0[15], b.v[8].x);
    fma2(a1, X1[15], b.v[8].x);
}

// Bit-exact rescore of pair gp for query xs (must mirror score_pair order).
__device__ __forceinline__ void rescore_pair(int gp, const float* xs,
                                             float& s0, float& s1) {
    const float2* pp = g_packed + (size_t)gp * SLOTS;
    float a0 = pp[0].x, a1 = pp[0].x;  // NOTE: both lanes init from .x like main loop
    // main loop init uses b.v[0].x = (pp[0].x, pp[0].y) packed; lane0 gets pp[0].x,
    // lane1 gets pp[0].y. Mirror that exactly:
    a0 = pp[0].x;
    a1 = pp[0].y;
#pragma unroll
    for (int d = 0; d < DIMS; ++d) {
        float2 y = pp[1 + d];
        a0 = fmaf(xs[d], y.x, a0);
        a1 = fmaf(xs[d], y.y, a1);
    }
    s0 = a0;
    s1 = a1;
}

// ---------------------------------------------------------------------------
// Each thread owns two query rows. Software-pipelined: prefetch pair p+1's
// smem data (9 LDS.128) while computing pair p's 34 FFMA2 — desynchronizes
// the per-iteration LDS wait that stalled all warps of an SMSP together.
// ---------------------------------------------------------------------------
__global__ void __launch_bounds__(BLOCK, 1)
nn_kernel(const float* __restrict__ x,
          const float* __restrict__ colors,
          float* __restrict__ out) {
    extern __shared__ unsigned long long s[];

    const int r0 = blockIdx.x * (BLOCK * QROWS) + threadIdx.x;
    const int r1 = r0 + BLOCK;

    unsigned long long X0[DIMS], X1[DIMS];
    {
        const float4* a = (const float4*)(x + (size_t)r0 * DIMS);
        const float4* b = (const float4*)(x + (size_t)r1 * DIMS);
#pragma unroll
        for (int i = 0; i < 4; ++i) {
            float4 v = a[i];
            X0[4 * i + 0] = bcast2(v.x);
            X0[4 * i + 1] = bcast2(v.y);
            X0[4 * i + 2] = bcast2(v.z);
            X0[4 * i + 3] = bcast2(v.w);
        }
#pragma unroll
        for (int i = 0; i < 4; ++i) {
            float4 v = b[i];
            X1[4 * i + 0] = bcast2(v.x);
            X1[4 * i + 1] = bcast2(v.y);
            X1[4 * i + 2] = bcast2(v.z);
            X1[4 * i + 3] = bcast2(v.w);
        }
    }

    float best0 = -CUDART_INF_F, best1 = -CUDART_INF_F;
    int rec0 = 0, rec1 = 0;  // global PAIR index of the last-improving pair

    for (int t = 0; t < NTILES; ++t) {
        __syncthreads();
        {
            const float4* src =
                (const float4*)(g_packed + (size_t)t * TILE_PAIRS * SLOTS);
            float4* dst = (float4*)s;
            const int nv4 = TILE_PAIRS * SLOTS / 2;  // 9000
            for (int i = threadIdx.x; i < nv4; i += BLOCK) dst[i] = src[i];
        }
        __syncthreads();

        const int pbase = t * TILE_PAIRS;
        const ulonglong2* sp = (const ulonglong2*)s;  // 9 ulonglong2 per pair

        Buf bufA, bufB;
        load_pair(bufA, sp);  // pair 0

#pragma unroll 1
        for (int p = 0; p < TILE_PAIRS; p += 2) {
            // --- prefetch pair p+1 into bufB, compute pair p from bufA ---
            load_pair(bufB, sp + (size_t)(p + 1) * 9);
            {
                unsigned long long a0, a1;
                score_pair(bufA, X0, X1, a0, a1);
                float l, h;
                unpack2(a0, l, h);
                float v = fmaxf(l, h);
                if (v > best0) rec0 = pbase + p;
                best0 = fmaxf(best0, v);
                unpack2(a1, l, h);
                v = fmaxf(l, h);
                if (v > best1) rec1 = pbase + p;
                best1 = fmaxf(best1, v);
            }
            // --- prefetch pair p+2 into bufA, compute pair p+1 from bufB ---
            {
                int pn = (p + 2 < TILE_PAIRS) ? (p + 2) : (TILE_PAIRS - 1);
                load_pair(bufA, sp + (size_t)pn * 9);
            }
            {
                unsigned long long a0, a1;
                score_pair(bufB, X0, X1, a0, a1);
                float l, h;
                unpack2(a0, l, h);
                float v = fmaxf(l, h);
                if (v > best0) rec0 = pbase + p + 1;
                best0 = fmaxf(best0, v);
                unpack2(a1, l, h);
                v = fmaxf(l, h);
                if (v > best1) rec1 = pbase + p + 1;
                best1 = fmaxf(best1, v);
            }
        }
    }

    // ---- Resolve exact vert index via bit-exact 2-candidate recompute ----
    {
        float xs[DIMS];
        const float4* xr = (const float4*)(x + (size_t)r0 * DIMS);
#pragma unroll
        for (int i = 0; i < 4; ++i) {
            float4 v = xr[i];
            xs[4 * i + 0] = v.x; xs[4 * i + 1] = v.y;
            xs[4 * i + 2] = v.z; xs[4 * i + 3] = v.w;
        }
        float a0, a1;
        rescore_pair(rec0, xs, a0, a1);
        int bi = 2 * rec0 + 1;
        if (a0 == best0) bi = 2 * rec0;
        const float* c = colors + (size_t)3 * bi;
        float* o = out + (size_t)3 * r0;
        o[0] = c[0]; o[1] = c[1]; o[2] = c[2];
    }
    {
        float xs[DIMS];
        const float4* xr = (const float4*)(x + (size_t)r1 * DIMS);
#pragma unroll
        for (int i = 0; i < 4; ++i) {
            float4 v = xr[i];
            xs[4 * i + 0] = v.x; xs[4 * i + 1] = v.y;
            xs[4 * i + 2] = v.z; xs[4 * i + 3] = v.w;
        }
        float a0, a1;
        rescore_pair(rec1, xs, a0, a1);
        int bi = 2 * rec1 + 1;
        if (a0 == best1) bi = 2 * rec1;
        const float* c = colors + (size_t)3 * bi;
        float* o = out + (size_t)3 * r1;
        o[0] = c[0]; o[1] = c[1]; o[2] = c[2];
    }
}

extern "C" void kernel_launch(void* const* d_in, const int* in_sizes, int n_in,
                              void* d_out, int out_size) {
    const float* cse    = (const float*)d_in[0];  // (M,16) f32
    const float* colors = (const float*)d_in[1];  // (N,3)  f32
    const float* vemb   = (const float*)d_in[2];  // (N,16) f32
    float* out = (float*)d_out;                   // (M,3)  f32

    cudaFuncSetAttribute(nn_kernel,
                         cudaFuncAttributeMaxDynamicSharedMemorySize,
                         SMEM_BYTES);

    prep_kernel<<<(NPAIRS + 255) / 256, 256>>>(vemb);
    nn_kernel<<<M_ROWS / (BLOCK * QROWS), BLOCK, SMEM_BYTES>>>(cse, colors, out);
}